// round 1
// baseline (speedup 1.0000x reference)
#include <cuda_runtime.h>

// ---------------- problem constants ----------------
#define NB   256      // batch
#define TQ   64       // quantized time
#define HD   256      // hidden dim
#define KC   8192     // n_embeddings

// output packing: (out, codebook_loss, commitment_loss, indices)
#define OUT_ELEMS   (256*1024*32)      // 8388608
#define LOSS_OFF    OUT_ELEMS
#define IDX_OFF     (OUT_ELEMS + 2)

// transposed-weight offsets
#define WT0  0          // enc0 32*3*64   = 6144
#define WT1  6144       // enc1 64*3*128  = 24576
#define WT2  30720      // enc2 128*3*256 = 98304
#define WTP  129024     // proj 256*1*256 = 65536
#define WTD0 194560     // dec0 256*3*256 = 196608
#define WTD1 391168     // dec1 256*3*128 = 98304
#define WTD2 489472     // dec2 128*3*64  = 24576
#define WTD3 514048     // dec3 64*3*32   = 6144
#define WTTOT 520192

// ---------------- device scratch ----------------
__device__ float g_h0[256*64*256];
__device__ float g_h1[256*128*128];
__device__ float g_h2[256*256*64];
__device__ float g_ze[256*256*64];
__device__ float g_zq[256*256*64];
__device__ float g_d0[256*256*128];
__device__ float g_d1[256*128*256];
__device__ float g_d2[256*64*512];
__device__ float g_wt[WTTOT];
__device__ float g_hn[KC];
__device__ int   g_idx[NB*TQ];
__device__ float g_loss[1];

// ---------------- weight transpose: w[co][ci][k] -> wt[(ci*K+k)][co] ----------------
__global__ void wtrans_kernel(const float* __restrict__ w, float* __restrict__ wt,
                              int Cout, int CinK) {
    int i = blockIdx.x * 256 + threadIdx.x;
    int tot = Cout * CinK;
    if (i >= tot) return;
    int co = i / CinK;
    int r  = i - co * CinK;
    wt[r * Cout + co] = w[i];
}

// ---------------- 0.5*||e||^2 ----------------
__global__ void enorm_kernel(const float* __restrict__ emb) {
    int n = blockIdx.x * 8 + (threadIdx.x >> 5);
    int lane = threadIdx.x & 31;
    const float* e = emb + (long)n * HD;
    float s = 0.f;
    #pragma unroll
    for (int c = lane; c < HD; c += 32) { float v = e[c]; s += v * v; }
    #pragma unroll
    for (int o = 16; o; o >>= 1) s += __shfl_xor_sync(0xffffffffu, s, o);
    if (lane == 0) g_hn[n] = 0.5f * s;
}

__global__ void zero_kernel() { if (threadIdx.x == 0) g_loss[0] = 0.f; }

// ---------------- generic direct conv1d ----------------
// out[b,co,to] = bias[co] + sum_{ci,k} in[b,ci,STRIDE*to+k-PAD] * w[co,ci,k]
template<int CIN, int COUT, int TT, int STRIDE, int KS, int PAD, bool RELU>
__global__ void conv1d_kernel(const float* __restrict__ in, const float* __restrict__ wt,
                              const float* __restrict__ bias, float* __restrict__ out,
                              int Tin, int Tout, int inB, int inC, int inT) {
    const int SW = STRIDE * (TT - 1) + KS;
    __shared__ float s_in[CIN][SW];
    int b   = blockIdx.x;
    int to0 = blockIdx.y * TT;
    int ti0 = STRIDE * to0 - PAD;

    for (int idx = threadIdx.x; idx < CIN * SW; idx += blockDim.x) {
        int ci = idx / SW, j = idx - ci * SW;
        int tg = ti0 + j;
        s_in[ci][j] = (tg >= 0 && tg < Tin)
            ? in[(long)b * inB + (long)ci * inC + (long)tg * inT] : 0.f;
    }
    __syncthreads();

    int co = threadIdx.x;
    float acc[TT];
    float bv = bias[co];
    #pragma unroll
    for (int t = 0; t < TT; t++) acc[t] = bv;

    for (int ci = 0; ci < CIN; ci++) {
        const float* sr = s_in[ci];
        if (KS == 3) {
            float w0 = wt[(ci * 3 + 0) * COUT + co];
            float w1 = wt[(ci * 3 + 1) * COUT + co];
            float w2 = wt[(ci * 3 + 2) * COUT + co];
            #pragma unroll
            for (int t = 0; t < TT; t++) {
                acc[t] = fmaf(w0, sr[STRIDE * t + 0], acc[t]);
                acc[t] = fmaf(w1, sr[STRIDE * t + 1], acc[t]);
                acc[t] = fmaf(w2, sr[STRIDE * t + 2], acc[t]);
            }
        } else {
            float w0 = wt[ci * COUT + co];
            #pragma unroll
            for (int t = 0; t < TT; t++) acc[t] = fmaf(w0, sr[t], acc[t]);
        }
    }
    long ob = (long)b * COUT * Tout + (long)co * Tout + to0;
    #pragma unroll
    for (int t = 0; t < TT; t++) {
        float v = acc[t];
        if (RELU) v = fmaxf(v, 0.f);
        out[ob + t] = v;
    }
}

// ---------------- deconv (ConvTranspose1d k=3 s=2 p=1 op=1 -> 2x upsample) ----------------
// even to: w1 * x[to/2];  odd to: w0 * x[(to-1)/2] + w2 * x[(to+1)/2]
template<int CIN, int COUT, int TT, int G, bool RELU>
__global__ void deconv1d_kernel(const float* __restrict__ in, const float* __restrict__ wt,
                                const float* __restrict__ bias, float* __restrict__ out,
                                int Tin, int Tout, long oB, long oCs, long oTs) {
    const int IW = G * TT / 2 + 1;
    __shared__ float s_in[CIN][IW];
    int b   = blockIdx.x;
    int to0 = blockIdx.y * (G * TT);
    int t0h = to0 >> 1;
    int nt  = blockDim.x * blockDim.y;
    int tid = threadIdx.y * blockDim.x + threadIdx.x;

    for (int idx = tid; idx < CIN * IW; idx += nt) {
        int ci = idx / IW, j = idx - ci * IW;
        int tg = t0h + j;
        s_in[ci][j] = (tg < Tin) ? in[(long)b * CIN * Tin + (long)ci * Tin + tg] : 0.f;
    }
    __syncthreads();

    int co   = threadIdx.x;
    int base = threadIdx.y * TT;   // even (TT even)
    float acc[TT];
    float bv = bias[co];
    #pragma unroll
    for (int t = 0; t < TT; t++) acc[t] = bv;

    for (int ci = 0; ci < CIN; ci++) {
        float w0 = wt[(ci * 3 + 0) * COUT + co];
        float w1 = wt[(ci * 3 + 1) * COUT + co];
        float w2 = wt[(ci * 3 + 2) * COUT + co];
        const float* sr = s_in[ci];
        #pragma unroll
        for (int t = 0; t < TT; t++) {
            int lo = base + t;
            if ((t & 1) == 0) {
                acc[t] = fmaf(w1, sr[lo >> 1], acc[t]);
            } else {
                acc[t] = fmaf(w0, sr[lo >> 1], acc[t]);
                acc[t] = fmaf(w2, sr[(lo >> 1) + 1], acc[t]);
            }
        }
    }
    #pragma unroll
    for (int t = 0; t < TT; t++) {
        float v = acc[t];
        if (RELU) v = fmaxf(v, 0.f);
        out[(long)b * oB + (long)co * oCs + (long)(to0 + base + t) * oTs] = v;
    }
}

// ---------------- VQ: fused GEMM (Z @ E^T) + argmax(score - 0.5||e||^2) ----------------
// one block per batch (64 rows), N streamed in 64-wide tiles, full K=256 resident.
__global__ void vq_kernel(const float* __restrict__ ze, const float* __restrict__ emb,
                          const float* __restrict__ hn, int* __restrict__ out_idx) {
    extern __shared__ float sm[];
    float* As = sm;                 // [256][64]  As[k*64 + m]
    float* Bs = sm + 256 * 64;      // [256][65]  Bs[k*65 + n]
    int b   = blockIdx.x;
    int tid = threadIdx.x;          // 256

    {   // load z tile (64 rows x 256 K), coalesced
        int r  = tid & 63;
        int c0 = tid >> 6;
        const float* zb = ze + (long)b * (HD * TQ);
        for (int c = c0; c < HD; c += 4)
            As[c * 64 + r] = zb[c * 64 + r];
    }
    __syncthreads();

    int tx = tid & 15, ty = tid >> 4;
    int ty4 = ty * 4, tx4 = tx * 4;
    float bval[4];
    int   bidx[4];
    #pragma unroll
    for (int i = 0; i < 4; i++) { bval[i] = -3.4e38f; bidx[i] = 0; }

    for (int n0 = 0; n0 < KC; n0 += 64) {
        const float* eb = emb + (long)n0 * HD;
        for (int nl = 0; nl < 64; nl++)
            Bs[tid * 65 + nl] = eb[nl * HD + tid];
        __syncthreads();

        float acc[4][4];
        #pragma unroll
        for (int i = 0; i < 4; i++)
            #pragma unroll
            for (int j = 0; j < 4; j++) acc[i][j] = 0.f;

        #pragma unroll 8
        for (int k = 0; k < HD; k++) {
            float4 av = *(const float4*)&As[k * 64 + ty4];
            float a[4] = {av.x, av.y, av.z, av.w};
            float bb[4];
            #pragma unroll
            for (int j = 0; j < 4; j++) bb[j] = Bs[k * 65 + tx4 + j];
            #pragma unroll
            for (int i = 0; i < 4; i++)
                #pragma unroll
                for (int j = 0; j < 4; j++)
                    acc[i][j] = fmaf(a[i], bb[j], acc[i][j]);
        }

        #pragma unroll
        for (int j = 0; j < 4; j++) {
            int n = n0 + tx4 + j;
            float h = hn[n];
            #pragma unroll
            for (int i = 0; i < 4; i++) {
                float s = acc[i][j] - h;
                if (s > bval[i]) { bval[i] = s; bidx[i] = n; }
            }
        }
        __syncthreads();
    }

    // cross-thread reduction (reuse Bs region)
    float* rv = Bs;                    // [64][16]
    int*   ri = (int*)(Bs + 1024);     // [64][16]
    #pragma unroll
    for (int i = 0; i < 4; i++) {
        int row = ty4 + i;
        rv[row * 16 + tx] = bval[i];
        ri[row * 16 + tx] = bidx[i];
    }
    __syncthreads();
    if (tid < 64) {
        float bv = rv[tid * 16];
        int   bi = ri[tid * 16];
        #pragma unroll
        for (int j = 1; j < 16; j++) {
            float v = rv[tid * 16 + j];
            int   ix = ri[tid * 16 + j];
            if (v > bv || (v == bv && ix < bi)) { bv = v; bi = ix; }
        }
        out_idx[b * 64 + tid] = bi;
    }
}

// ---------------- gather z_q + loss sum ----------------
__global__ void loss_gather_kernel(const float* __restrict__ ze, const float* __restrict__ emb) {
    int m = blockIdx.x;
    int b = m >> 6, t = m & 63;
    int c = threadIdx.x;                      // 256
    int e = g_idx[m];
    float q = emb[(long)e * HD + c];
    long zoff = (long)b * (HD * TQ) + (long)c * TQ + t;
    float z = ze[zoff];
    g_zq[zoff] = q;
    float d = z - q;
    float s = d * d;
    #pragma unroll
    for (int o = 16; o; o >>= 1) s += __shfl_down_sync(0xffffffffu, s, o);
    __shared__ float ws[8];
    if ((c & 31) == 0) ws[c >> 5] = s;
    __syncthreads();
    if (c == 0) {
        float tot = 0.f;
        #pragma unroll
        for (int i = 0; i < 8; i++) tot += ws[i];
        atomicAdd(g_loss, tot);
    }
}

__global__ void finalize_kernel(float* out) {
    float l = g_loss[0] * (1.f / 4194304.f);   // mean over B*H*TQ
    out[LOSS_OFF + 0] = l;   // codebook_loss
    out[LOSS_OFF + 1] = l;   // commitment_loss
}

__global__ void idxout_kernel(float* out) {
    int m = blockIdx.x * 256 + threadIdx.x;
    out[IDX_OFF + m] = (float)g_idx[m];
}

// ---------------- launch ----------------
extern "C" void kernel_launch(void* const* d_in, const int* in_sizes, int n_in,
                              void* d_out, int out_size) {
    const float* x   = (const float*)d_in[0];
    const float* ew0 = (const float*)d_in[1];  const float* eb0 = (const float*)d_in[2];
    const float* ew1 = (const float*)d_in[3];  const float* eb1 = (const float*)d_in[4];
    const float* ew2 = (const float*)d_in[5];  const float* eb2 = (const float*)d_in[6];
    const float* pw  = (const float*)d_in[7];  const float* pb  = (const float*)d_in[8];
    const float* emb = (const float*)d_in[9];
    const float* dw0 = (const float*)d_in[10]; const float* db0 = (const float*)d_in[11];
    const float* dw1 = (const float*)d_in[12]; const float* db1 = (const float*)d_in[13];
    const float* dw2 = (const float*)d_in[14]; const float* db2 = (const float*)d_in[15];
    const float* dw3 = (const float*)d_in[16]; const float* db3 = (const float*)d_in[17];
    float* out = (float*)d_out;

    void* p;
    cudaGetSymbolAddress(&p, g_wt);  float* wt = (float*)p;
    cudaGetSymbolAddress(&p, g_h0);  float* h0 = (float*)p;
    cudaGetSymbolAddress(&p, g_h1);  float* h1 = (float*)p;
    cudaGetSymbolAddress(&p, g_h2);  float* h2 = (float*)p;
    cudaGetSymbolAddress(&p, g_ze);  float* ze = (float*)p;
    cudaGetSymbolAddress(&p, g_zq);  float* zq = (float*)p;
    cudaGetSymbolAddress(&p, g_d0);  float* d0 = (float*)p;
    cudaGetSymbolAddress(&p, g_d1);  float* d1 = (float*)p;
    cudaGetSymbolAddress(&p, g_d2);  float* d2 = (float*)p;
    cudaGetSymbolAddress(&p, g_hn);  float* hn = (float*)p;
    cudaGetSymbolAddress(&p, g_idx); int*   ix = (int*)p;

    cudaFuncSetAttribute(vq_kernel, cudaFuncAttributeMaxDynamicSharedMemorySize, 132096);

    // prep: weight transposes, code norms, zero loss
    wtrans_kernel<<<(6144   + 255)/256, 256>>>(ew0, wt + WT0,  64,  32*3);
    wtrans_kernel<<<(24576  + 255)/256, 256>>>(ew1, wt + WT1,  128, 64*3);
    wtrans_kernel<<<(98304  + 255)/256, 256>>>(ew2, wt + WT2,  256, 128*3);
    wtrans_kernel<<<(65536  + 255)/256, 256>>>(pw,  wt + WTP,  256, 256);
    wtrans_kernel<<<(196608 + 255)/256, 256>>>(dw0, wt + WTD0, 256, 256*3);
    wtrans_kernel<<<(98304  + 255)/256, 256>>>(dw1, wt + WTD1, 128, 256*3);
    wtrans_kernel<<<(24576  + 255)/256, 256>>>(dw2, wt + WTD2, 64,  128*3);
    wtrans_kernel<<<(6144   + 255)/256, 256>>>(dw3, wt + WTD3, 32,  64*3);
    enorm_kernel<<<KC/8, 256>>>(emb);
    zero_kernel<<<1, 32>>>();

    // encoder
    conv1d_kernel<32, 64, 16, 2, 3, 1, true ><<<dim3(NB,16), 64 >>>(x,  wt+WT0, eb0, h0, 512, 256, 512*32, 1,  32);
    conv1d_kernel<64, 128,16, 2, 3, 1, true ><<<dim3(NB, 8), 128>>>(h0, wt+WT1, eb1, h1, 256, 128, 64*256, 256, 1);
    conv1d_kernel<128,256,16, 2, 3, 1, true ><<<dim3(NB, 4), 256>>>(h1, wt+WT2, eb2, h2, 128, 64,  128*128,128, 1);
    conv1d_kernel<256,256,16, 1, 1, 0, false><<<dim3(NB, 4), 256>>>(h2, wt+WTP, pb,  ze, 64,  64,  256*64, 64,  1);

    // vector quantizer
    vq_kernel<<<NB, 256, 132096>>>(ze, emb, hn, ix);
    loss_gather_kernel<<<NB*TQ, 256>>>(ze, emb);

    // decoder
    deconv1d_kernel<256,256,16,1, true ><<<dim3(NB, 8), dim3(256,1)>>>(zq, wt+WTD0, db0, d0, 64,  128,  256*128, 128, 1);
    deconv1d_kernel<256,128,16,1, true ><<<dim3(NB,16), dim3(128,1)>>>(d0, wt+WTD1, db1, d1, 128, 256,  128*256, 256, 1);
    deconv1d_kernel<128,64, 16,2, true ><<<dim3(NB,16), dim3(64, 2)>>>(d1, wt+WTD2, db2, d2, 256, 512,  64*512,  512, 1);
    deconv1d_kernel<64, 32, 16,4, false><<<dim3(NB,16), dim3(32, 4)>>>(d2, wt+WTD3, db3, out,512, 1024, 1024*32, 1,  32);

    // scalar outputs
    finalize_kernel<<<1, 1>>>(out);
    idxout_kernel<<<64, 256>>>(out);
}

// round 2
// speedup vs baseline: 1.1296x; 1.1296x over previous
#include <cuda_runtime.h>

// ---------------- problem constants ----------------
#define NB   256      // batch
#define TQ   64       // quantized time
#define HD   256      // hidden dim
#define KC   8192     // n_embeddings

// output packing: (out, codebook_loss, commitment_loss, indices)
#define OUT_ELEMS   (256*1024*32)      // 8388608
#define LOSS_OFF    OUT_ELEMS
#define IDX_OFF     (OUT_ELEMS + 2)

// transposed-weight offsets
#define WT0  0          // enc0 32*3*64   = 6144
#define WT1  6144       // enc1 64*3*128  = 24576
#define WT2  30720      // enc2 128*3*256 = 98304
#define WTP  129024     // proj 256*1*256 = 65536
#define WTD0 194560     // dec0 256*3*256 = 196608
#define WTD1 391168     // dec1 256*3*128 = 98304
#define WTD2 489472     // dec2 128*3*64  = 24576
#define WTD3 514048     // dec3 64*3*32   = 6144
#define WTTOT 520192

typedef unsigned long long u64;

// ---------------- f32x2 helpers (sm_103a packed fp32, bit-identical to 2x scalar) ----
__device__ __forceinline__ u64 ffma2(u64 a, u64 b, u64 c) {
    u64 d;
    asm("fma.rn.f32x2 %0, %1, %2, %3;" : "=l"(d) : "l"(a), "l"(b), "l"(c));
    return d;
}
__device__ __forceinline__ u64 pack2(float lo, float hi) {
    u64 d;
    asm("mov.b64 %0, {%1, %2};" : "=l"(d) : "f"(lo), "f"(hi));
    return d;
}
__device__ __forceinline__ float f2lo(u64 v) {
    float lo, hi;
    asm("mov.b64 {%0, %1}, %2;" : "=f"(lo), "=f"(hi) : "l"(v));
    return lo;
}
__device__ __forceinline__ float f2hi(u64 v) {
    float lo, hi;
    asm("mov.b64 {%0, %1}, %2;" : "=f"(lo), "=f"(hi) : "l"(v));
    return hi;
}
__device__ __forceinline__ void cp_async4(unsigned smem_addr, const void* gptr) {
    asm volatile("cp.async.ca.shared.global [%0], [%1], 4;" :: "r"(smem_addr), "l"(gptr));
}
__device__ __forceinline__ void cp_commit() {
    asm volatile("cp.async.commit_group;" ::: "memory");
}
__device__ __forceinline__ void cp_wait0() {
    asm volatile("cp.async.wait_group 0;" ::: "memory");
}

// ---------------- device scratch ----------------
__device__ float g_h0[256*64*256];
__device__ float g_h1[256*128*128];
__device__ float g_h2[256*256*64];
__device__ float g_ze[256*256*64];
__device__ float g_zq[256*256*64];
__device__ float g_d0[256*256*128];
__device__ float g_d1[256*128*256];
__device__ float g_d2[256*64*512];
__device__ float g_wt[WTTOT];
__device__ float g_hn[KC];
__device__ int   g_idx[NB*TQ];
__device__ float g_loss[1];

// ---------------- weight transpose: w[co][ci][k] -> wt[(ci*K+k)][co] ----------------
__global__ void wtrans_kernel(const float* __restrict__ w, float* __restrict__ wt,
                              int Cout, int CinK) {
    int i = blockIdx.x * 256 + threadIdx.x;
    int tot = Cout * CinK;
    if (i >= tot) return;
    int co = i / CinK;
    int r  = i - co * CinK;
    wt[r * Cout + co] = w[i];
}

// ---------------- 0.5*||e||^2 ----------------
__global__ void enorm_kernel(const float* __restrict__ emb) {
    int n = blockIdx.x * 8 + (threadIdx.x >> 5);
    int lane = threadIdx.x & 31;
    const float* e = emb + (long)n * HD;
    float s = 0.f;
    #pragma unroll
    for (int c = lane; c < HD; c += 32) { float v = e[c]; s += v * v; }
    #pragma unroll
    for (int o = 16; o; o >>= 1) s += __shfl_xor_sync(0xffffffffu, s, o);
    if (lane == 0) g_hn[n] = 0.5f * s;
}

__global__ void zero_kernel() { if (threadIdx.x == 0) g_loss[0] = 0.f; }

// ---------------- generic direct conv1d (k=3, strided; used by encoder) ----------------
template<int CIN, int COUT, int TT, int STRIDE, int PAD, bool RELU>
__global__ void conv1d_kernel(const float* __restrict__ in, const float* __restrict__ wt,
                              const float* __restrict__ bias, float* __restrict__ out,
                              int Tin, int Tout, int inB, int inC, int inT) {
    const int SW = STRIDE * (TT - 1) + 3;
    __shared__ float s_in[CIN][SW];
    int b   = blockIdx.x;
    int to0 = blockIdx.y * TT;
    int ti0 = STRIDE * to0 - PAD;

    for (int idx = threadIdx.x; idx < CIN * SW; idx += blockDim.x) {
        int ci = idx / SW, j = idx - ci * SW;
        int tg = ti0 + j;
        s_in[ci][j] = (tg >= 0 && tg < Tin)
            ? in[(long)b * inB + (long)ci * inC + (long)tg * inT] : 0.f;
    }
    __syncthreads();

    int co = threadIdx.x;
    float acc[TT];
    float bv = bias[co];
    #pragma unroll
    for (int t = 0; t < TT; t++) acc[t] = bv;

    for (int ci = 0; ci < CIN; ci++) {
        const float* sr = s_in[ci];
        float w0 = wt[(ci * 3 + 0) * COUT + co];
        float w1 = wt[(ci * 3 + 1) * COUT + co];
        float w2 = wt[(ci * 3 + 2) * COUT + co];
        #pragma unroll
        for (int t = 0; t < TT; t++) {
            acc[t] = fmaf(w0, sr[STRIDE * t + 0], acc[t]);
            acc[t] = fmaf(w1, sr[STRIDE * t + 1], acc[t]);
            acc[t] = fmaf(w2, sr[STRIDE * t + 2], acc[t]);
        }
    }
    long ob = (long)b * COUT * Tout + (long)co * Tout + to0;
    #pragma unroll
    for (int t = 0; t < TT; t++) {
        float v = acc[t];
        if (RELU) v = fmaxf(v, 0.f);
        out[ob + t] = v;
    }
}

// ---------------- 1x1 projection conv, f32x2 ----------------
__global__ void proj_kernel(const float* __restrict__ in, const float* __restrict__ wt,
                            const float* __restrict__ bias, float* __restrict__ out) {
    // CIN=COUT=256, TT=16, Tin=Tout=64
    __shared__ float s_in[256][16];
    int b   = blockIdx.x;
    int to0 = blockIdx.y * 16;
    for (int idx = threadIdx.x; idx < 256 * 16; idx += 256) {
        int ci = idx >> 4, j = idx & 15;
        s_in[ci][j] = in[(long)b * (256 * 64) + ci * 64 + to0 + j];
    }
    __syncthreads();

    int co = threadIdx.x;
    float bv = bias[co];
    u64 acc[8];
    #pragma unroll
    for (int p = 0; p < 8; p++) acc[p] = pack2(bv, bv);

    for (int ci = 0; ci < 256; ci++) {
        float w = wt[ci * 256 + co];
        u64 ws = pack2(w, w);
        const u64* xr = (const u64*)&s_in[ci][0];
        #pragma unroll
        for (int p = 0; p < 8; p++) acc[p] = ffma2(ws, xr[p], acc[p]);
    }
    long ob = (long)b * (256 * 64) + (long)co * 64 + to0;
    #pragma unroll
    for (int p = 0; p < 8; p++) {
        out[ob + 2 * p + 0] = f2lo(acc[p]);
        out[ob + 2 * p + 1] = f2hi(acc[p]);
    }
}

// ---------------- deconv (ConvTranspose1d k=3 s=2 p=1 op=1), f32x2 ----------------
// even to: w1*x[to/2]; odd to: w0*x[(to-1)/2] + w2*x[(to+1)/2]
template<int CIN, int COUT, int TT, int G, bool RELU>
__global__ void deconv1d_kernel(const float* __restrict__ in, const float* __restrict__ wt,
                                const float* __restrict__ bias, float* __restrict__ out,
                                int Tin, long oB, long oCs, long oTs) {
    const int IW  = G * TT / 2 + 1;
    const int IWP = (IW | 1) + 1;   // even row stride -> 8B-aligned rows
    __shared__ float s_in[CIN][IWP];
    int b   = blockIdx.x;
    int to0 = blockIdx.y * (G * TT);
    int t0h = to0 >> 1;
    int nt  = blockDim.x * blockDim.y;
    int tid = threadIdx.y * blockDim.x + threadIdx.x;

    for (int idx = tid; idx < CIN * IW; idx += nt) {
        int ci = idx / IW, j = idx - ci * IW;
        int tg = t0h + j;
        s_in[ci][j] = (tg < Tin) ? in[(long)b * CIN * Tin + (long)ci * Tin + tg] : 0.f;
    }
    __syncthreads();

    int co   = threadIdx.x;
    int base = threadIdx.y * TT;   // even
    int H0   = base >> 1;          // = 8*threadIdx.y, even
    float bv = bias[co];
    u64 aE[TT / 4], aO[TT / 4];
    #pragma unroll
    for (int p = 0; p < TT / 4; p++) { aE[p] = pack2(bv, bv); aO[p] = pack2(bv, bv); }

    for (int ci = 0; ci < CIN; ci++) {
        float w0 = wt[(ci * 3 + 0) * COUT + co];
        float w1 = wt[(ci * 3 + 1) * COUT + co];
        float w2 = wt[(ci * 3 + 2) * COUT + co];
        u64 w00 = pack2(w0, w0), w11 = pack2(w1, w1), w22 = pack2(w2, w2);
        const float2* xr = (const float2*)(&s_in[ci][H0]);   // H0 even, row 8B-aligned
        float2 xp[4];
        #pragma unroll
        for (int p = 0; p < 4; p++) xp[p] = xr[p];
        float x8 = s_in[ci][H0 + 8];
        #pragma unroll
        for (int p = 0; p < 4; p++) {
            u64 X = pack2(xp[p].x, xp[p].y);
            u64 Z = pack2(xp[p].y, (p < 3) ? xp[p + 1].x : x8);
            aE[p] = ffma2(w11, X, aE[p]);
            aO[p] = ffma2(w00, X, aO[p]);
            aO[p] = ffma2(w22, Z, aO[p]);
        }
    }
    long ob = (long)b * oB + (long)co * oCs;
    #pragma unroll
    for (int p = 0; p < 4; p++) {
        float v0 = f2lo(aE[p]), v1 = f2lo(aO[p]), v2 = f2hi(aE[p]), v3 = f2hi(aO[p]);
        if (RELU) { v0 = fmaxf(v0, 0.f); v1 = fmaxf(v1, 0.f); v2 = fmaxf(v2, 0.f); v3 = fmaxf(v3, 0.f); }
        long t = to0 + base + 4 * p;
        out[ob + (t + 0) * oTs] = v0;
        out[ob + (t + 1) * oTs] = v1;
        out[ob + (t + 2) * oTs] = v2;
        out[ob + (t + 3) * oTs] = v3;
    }
}

// ---------------- VQ: fused GEMM (Z @ E^T) + argmax(score - 0.5||e||^2), f32x2 ----
// one block per batch (64 rows); N streamed in 64-wide tiles, double-buffered
// via cp.async; full K=256 resident in smem.
#define BSTR 66
__global__ void vq_kernel(const float* __restrict__ ze, const float* __restrict__ emb,
                          const float* __restrict__ hn, int* __restrict__ out_idx) {
    extern __shared__ float sm[];
    float* As  = sm;                       // [256][64]  As[k*64+m]
    float* Bs0 = sm + 256 * 64;            // [256][BSTR] k-major
    float* Bs1 = Bs0 + 256 * BSTR;
    int b   = blockIdx.x;
    int tid = threadIdx.x;                 // 256

    {   // load z tile (64 rows x 256 K), coalesced
        int r  = tid & 63;
        int c0 = tid >> 6;
        const float* zb = ze + (long)b * (HD * TQ);
        for (int c = c0; c < HD; c += 4)
            As[c * 64 + r] = zb[c * 64 + r];
    }

    // prefetch tile 0 into Bs0: thread tid owns k=tid, iterates n
    {
        const float* eb = emb + tid;       // emb[n][k], k=tid
        unsigned dst = (unsigned)__cvta_generic_to_shared(Bs0 + tid * BSTR);
        #pragma unroll 8
        for (int nl = 0; nl < 64; nl++)
            cp_async4(dst + 4u * nl, eb + (long)nl * HD);
        cp_commit();
    }
    cp_wait0();
    __syncthreads();

    int tx = tid & 15, ty = tid >> 4;
    int ty4 = ty * 4, tx4 = tx * 4;
    float bval[4];
    int   bidx[4];
    #pragma unroll
    for (int i = 0; i < 4; i++) { bval[i] = -3.4e38f; bidx[i] = 0; }

    const float4* hn4 = (const float4*)hn;

    for (int tile = 0; tile < KC / 64; tile++) {
        const float* Bc = (tile & 1) ? Bs1 : Bs0;
        float*       Bn = (tile & 1) ? Bs0 : Bs1;
        bool more = (tile + 1) < KC / 64;
        if (more) {   // async prefetch next tile
            const float* eb = emb + (long)(tile + 1) * 64 * HD + tid;
            unsigned dst = (unsigned)__cvta_generic_to_shared(Bn + tid * BSTR);
            #pragma unroll 8
            for (int nl = 0; nl < 64; nl++)
                cp_async4(dst + 4u * nl, eb + (long)nl * HD);
            cp_commit();
        }

        u64 acc[4][2];
        #pragma unroll
        for (int i = 0; i < 4; i++) { acc[i][0] = 0ull; acc[i][1] = 0ull; }

        #pragma unroll 8
        for (int k = 0; k < HD; k++) {
            float4 av = *(const float4*)&As[k * 64 + ty4];
            u64 b01 = *(const u64*)&Bc[k * BSTR + tx4];
            u64 b23 = *(const u64*)&Bc[k * BSTR + tx4 + 2];
            u64 a0 = pack2(av.x, av.x);
            u64 a1 = pack2(av.y, av.y);
            u64 a2 = pack2(av.z, av.z);
            u64 a3 = pack2(av.w, av.w);
            acc[0][0] = ffma2(a0, b01, acc[0][0]); acc[0][1] = ffma2(a0, b23, acc[0][1]);
            acc[1][0] = ffma2(a1, b01, acc[1][0]); acc[1][1] = ffma2(a1, b23, acc[1][1]);
            acc[2][0] = ffma2(a2, b01, acc[2][0]); acc[2][1] = ffma2(a2, b23, acc[2][1]);
            acc[3][0] = ffma2(a3, b01, acc[3][0]); acc[3][1] = ffma2(a3, b23, acc[3][1]);
        }

        int n0 = tile * 64;
        float4 h = hn4[(n0 + tx4) >> 2];
        #pragma unroll
        for (int i = 0; i < 4; i++) {
            float s0 = f2lo(acc[i][0]) - h.x;
            float s1 = f2hi(acc[i][0]) - h.y;
            float s2 = f2lo(acc[i][1]) - h.z;
            float s3 = f2hi(acc[i][1]) - h.w;
            if (s0 > bval[i]) { bval[i] = s0; bidx[i] = n0 + tx4 + 0; }
            if (s1 > bval[i]) { bval[i] = s1; bidx[i] = n0 + tx4 + 1; }
            if (s2 > bval[i]) { bval[i] = s2; bidx[i] = n0 + tx4 + 2; }
            if (s3 > bval[i]) { bval[i] = s3; bidx[i] = n0 + tx4 + 3; }
        }
        cp_wait0();
        __syncthreads();
    }

    // cross-thread reduction (As region no longer needed)
    float* rv = As;                    // [64][16]
    int*   ri = (int*)(As + 1024);     // [64][16]
    #pragma unroll
    for (int i = 0; i < 4; i++) {
        int row = ty4 + i;
        rv[row * 16 + tx] = bval[i];
        ri[row * 16 + tx] = bidx[i];
    }
    __syncthreads();
    if (tid < 64) {
        float bv = rv[tid * 16];
        int   bi = ri[tid * 16];
        #pragma unroll
        for (int j = 1; j < 16; j++) {
            float v  = rv[tid * 16 + j];
            int   ix = ri[tid * 16 + j];
            if (v > bv || (v == bv && ix < bi)) { bv = v; bi = ix; }
        }
        out_idx[b * 64 + tid] = bi;
    }
}

// ---------------- gather z_q + loss sum ----------------
__global__ void loss_gather_kernel(const float* __restrict__ ze, const float* __restrict__ emb) {
    int m = blockIdx.x;
    int b = m >> 6, t = m & 63;
    int c = threadIdx.x;                      // 256
    int e = g_idx[m];
    float q = emb[(long)e * HD + c];
    long zoff = (long)b * (HD * TQ) + (long)c * TQ + t;
    float z = ze[zoff];
    g_zq[zoff] = q;
    float d = z - q;
    float s = d * d;
    #pragma unroll
    for (int o = 16; o; o >>= 1) s += __shfl_down_sync(0xffffffffu, s, o);
    __shared__ float ws[8];
    if ((c & 31) == 0) ws[c >> 5] = s;
    __syncthreads();
    if (c == 0) {
        float tot = 0.f;
        #pragma unroll
        for (int i = 0; i < 8; i++) tot += ws[i];
        atomicAdd(g_loss, tot);
    }
}

__global__ void finalize_kernel(float* out) {
    float l = g_loss[0] * (1.f / 4194304.f);   // mean over B*H*TQ
    out[LOSS_OFF + 0] = l;   // codebook_loss
    out[LOSS_OFF + 1] = l;   // commitment_loss
}

__global__ void idxout_kernel(float* out) {
    int m = blockIdx.x * 256 + threadIdx.x;
    out[IDX_OFF + m] = (float)g_idx[m];
}

// ---------------- launch ----------------
extern "C" void kernel_launch(void* const* d_in, const int* in_sizes, int n_in,
                              void* d_out, int out_size) {
    const float* x   = (const float*)d_in[0];
    const float* ew0 = (const float*)d_in[1];  const float* eb0 = (const float*)d_in[2];
    const float* ew1 = (const float*)d_in[3];  const float* eb1 = (const float*)d_in[4];
    const float* ew2 = (const float*)d_in[5];  const float* eb2 = (const float*)d_in[6];
    const float* pw  = (const float*)d_in[7];  const float* pb  = (const float*)d_in[8];
    const float* emb = (const float*)d_in[9];
    const float* dw0 = (const float*)d_in[10]; const float* db0 = (const float*)d_in[11];
    const float* dw1 = (const float*)d_in[12]; const float* db1 = (const float*)d_in[13];
    const float* dw2 = (const float*)d_in[14]; const float* db2 = (const float*)d_in[15];
    const float* dw3 = (const float*)d_in[16]; const float* db3 = (const float*)d_in[17];
    float* out = (float*)d_out;

    void* p;
    cudaGetSymbolAddress(&p, g_wt);  float* wt = (float*)p;
    cudaGetSymbolAddress(&p, g_h0);  float* h0 = (float*)p;
    cudaGetSymbolAddress(&p, g_h1);  float* h1 = (float*)p;
    cudaGetSymbolAddress(&p, g_h2);  float* h2 = (float*)p;
    cudaGetSymbolAddress(&p, g_ze);  float* ze = (float*)p;
    cudaGetSymbolAddress(&p, g_zq);  float* zq = (float*)p;
    cudaGetSymbolAddress(&p, g_d0);  float* d0 = (float*)p;
    cudaGetSymbolAddress(&p, g_d1);  float* d1 = (float*)p;
    cudaGetSymbolAddress(&p, g_d2);  float* d2 = (float*)p;
    cudaGetSymbolAddress(&p, g_hn);  float* hn = (float*)p;
    cudaGetSymbolAddress(&p, g_idx); int*   ix = (int*)p;

    const int VQ_SMEM = 256 * 64 * 4 + 2 * 256 * BSTR * 4;   // 200704
    cudaFuncSetAttribute(vq_kernel, cudaFuncAttributeMaxDynamicSharedMemorySize, VQ_SMEM);

    // prep: weight transposes, code norms, zero loss
    wtrans_kernel<<<(6144   + 255)/256, 256>>>(ew0, wt + WT0,  64,  32*3);
    wtrans_kernel<<<(24576  + 255)/256, 256>>>(ew1, wt + WT1,  128, 64*3);
    wtrans_kernel<<<(98304  + 255)/256, 256>>>(ew2, wt + WT2,  256, 128*3);
    wtrans_kernel<<<(65536  + 255)/256, 256>>>(pw,  wt + WTP,  256, 256);
    wtrans_kernel<<<(196608 + 255)/256, 256>>>(dw0, wt + WTD0, 256, 256*3);
    wtrans_kernel<<<(98304  + 255)/256, 256>>>(dw1, wt + WTD1, 128, 256*3);
    wtrans_kernel<<<(24576  + 255)/256, 256>>>(dw2, wt + WTD2, 64,  128*3);
    wtrans_kernel<<<(6144   + 255)/256, 256>>>(dw3, wt + WTD3, 32,  64*3);
    enorm_kernel<<<KC/8, 256>>>(emb);
    zero_kernel<<<1, 32>>>();

    // encoder
    conv1d_kernel<32, 64, 16, 2, 1, true ><<<dim3(NB,16), 64 >>>(x,  wt+WT0, eb0, h0, 512, 256, 512*32, 1,  32);
    conv1d_kernel<64, 128,16, 2, 1, true ><<<dim3(NB, 8), 128>>>(h0, wt+WT1, eb1, h1, 256, 128, 64*256, 256, 1);
    conv1d_kernel<128,256,16, 2, 1, true ><<<dim3(NB, 4), 256>>>(h1, wt+WT2, eb2, h2, 128, 64,  128*128,128, 1);
    proj_kernel<<<dim3(NB, 4), 256>>>(h2, wt+WTP, pb, ze);

    // vector quantizer
    vq_kernel<<<NB, 256, VQ_SMEM>>>(ze, emb, hn, ix);
    loss_gather_kernel<<<NB*TQ, 256>>>(ze, emb);

    // decoder
    deconv1d_kernel<256,256,16,1, true ><<<dim3(NB, 8), dim3(256,1)>>>(zq, wt+WTD0, db0, d0, 64,  256*128, 128, 1);
    deconv1d_kernel<256,128,16,1, true ><<<dim3(NB,16), dim3(128,1)>>>(d0, wt+WTD1, db1, d1, 128, 128*256, 256, 1);
    deconv1d_kernel<128,64, 16,2, true ><<<dim3(NB,16), dim3(64, 2)>>>(d1, wt+WTD2, db2, d2, 256, 64*512,  512, 1);
    deconv1d_kernel<64, 32, 16,4, false><<<dim3(NB,16), dim3(32, 4)>>>(d2, wt+WTD3, db3, out,512, 1024*32, 1,  32);

    // scalar outputs
    finalize_kernel<<<1, 1>>>(out);
    idxout_kernel<<<64, 256>>>(out);
}